// round 14
// baseline (speedup 1.0000x reference)
#include <cuda_runtime.h>

// StackedLSTM: B=2048, T=2048, D=H=6, 2 layers, softmax over final h of layer 1.
// R6 structure (16 lanes/batch: lanes 0-7 layer 0, 8-15 layer 1, smem exchange,
// k-pair f32x2 math, prescaled sigmoid) + TWO independent batch "sets" per
// thread (set A = batch g, set B = batch g+1024). The two chains interleave in
// one instruction stream via the scoreboard; one __syncwarp serves both sets.
// 16384 threads = 512 warps = 1 warp/SMSP on 128 SMs.

#define TT 2048

typedef unsigned long long u64;
typedef ulonglong2 u64x2;

__device__ __forceinline__ u64 pack2(float lo, float hi) {
    u64 r; asm("mov.b64 %0, {%1, %2};" : "=l"(r) : "f"(lo), "f"(hi)); return r;
}
__device__ __forceinline__ void unpack2(u64 v, float& lo, float& hi) {
    asm("mov.b64 {%0, %1}, %2;" : "=f"(lo), "=f"(hi) : "l"(v));
}
__device__ __forceinline__ u64 ffma2(u64 a, u64 b, u64 c) {
    u64 d; asm("fma.rn.f32x2 %0, %1, %2, %3;" : "=l"(d) : "l"(a), "l"(b), "l"(c));
    return d;
}
__device__ __forceinline__ u64 fadd2(u64 a, u64 b) {
    u64 d; asm("add.rn.f32x2 %0, %1, %2;" : "=l"(d) : "l"(a), "l"(b)); return d;
}
__device__ __forceinline__ float tanh_f(float x) {
    float y; asm("tanh.approx.f32 %0, %1;" : "=f"(y) : "f"(x)); return y;
}

struct CellW {
    u64 wx[4][3];   // input-side weight k-pairs per gate (i,f,g,o), prescaled
    u64 wh[4][3];   // recurrent-side weight k-pairs
    u64 b[4];       // {bias, 0}
};

__device__ __forceinline__ void cell(const CellW& W, const u64* in, const u64* rg,
                                     float& h, float& c) {
    float g[4];
#pragma unroll
    for (int q = 0; q < 4; ++q) {
        u64 ax = ffma2(W.wx[q][0], in[0], W.b[q]);
        ax     = ffma2(W.wx[q][1], in[1], ax);
        ax     = ffma2(W.wx[q][2], in[2], ax);
        u64 ah = ffma2(W.wh[q][0], rg[0], 0ull);
        ah     = ffma2(W.wh[q][1], rg[1], ah);
        ah     = ffma2(W.wh[q][2], rg[2], ah);
        u64 s2 = fadd2(ax, ah);
        float lo, hi; unpack2(s2, lo, hi);
        g[q] = lo + hi;
    }
    float gi = fmaf(tanh_f(g[0]), 0.5f, 0.5f);
    float gf = fmaf(tanh_f(g[1]), 0.5f, 0.5f);
    float gg = tanh_f(g[2]);
    float go = fmaf(tanh_f(g[3]), 0.5f, 0.5f);
    c = fmaf(gf, c, gi * gg);
    h = go * tanh_f(c);
}

// One set's sub-iteration: read state at this parity, run cell, write h into the
// other parity. base/wbase: the group's 16-float regions. No sync inside.
template <bool ZF>
__device__ __forceinline__ void one(const CellW& W, bool isL1, int ro, int slot,
                                    const float* base, float* wbase,
                                    const u64* xp, float& h, float& c) {
    u64x2 a = *(const u64x2*)base;           // h0[0..3]
    u64   a2 = ((const u64*)base)[2];        // h0[4..5]
    u64x2 r = *(const u64x2*)(base + ro);    // own-layer state (ro=0 or 8, 16B/32B aligned)
    u64   r2 = ((const u64*)(base + ro))[2];
    u64 in[3] = { isL1 ? a.x : xp[0], isL1 ? a.y : xp[1], isL1 ? a2 : xp[2] };
    u64 rg[3] = { r.x, r.y, r2 };
    cell(W, in, rg, h, c);
    if (ZF && isL1) { h = 0.f; c = 0.f; }    // t=0: layer-1 step is spurious
    wbase[slot] = h;
}

// Load ONE timestep of x (6 floats = 3 u64). 24B stride; 48B blocks of 2 steps
// keep the first load 16B-aligned on even t, 8B-aligned on odd t -> use 8B loads.
__device__ __forceinline__ void loadstep(const float* __restrict__ xb, int t, u64* u) {
    const u64* p = (const u64*)(xb + 6 * t);  // 8B aligned always
    u[0] = p[0]; u[1] = p[1]; u[2] = p[2];
}

__global__ void __launch_bounds__(128, 1)
stacked_lstm_kernel(const float* __restrict__ x,
                    const float* __restrict__ Wi0, const float* __restrict__ Wh0,
                    const float* __restrict__ bi0, const float* __restrict__ bh0,
                    const float* __restrict__ Wi1, const float* __restrict__ Wh1,
                    const float* __restrict__ bi1, const float* __restrict__ bh1,
                    float* __restrict__ out) {
    const int lane  = threadIdx.x & 31;
    const bool isL1 = (lane & 8) != 0;
    const int j     = lane & 7;
    const int jj    = (j < 6) ? j : 5;
    const int ro    = isL1 ? 8 : 0;
    const int slot  = ro + j;
    const int wg    = threadIdx.x >> 4;     // group within block (0..7)
    const int g     = (blockIdx.x * blockDim.x + threadIdx.x) >> 4;  // 0..1023
    const int bA    = g;
    const int bB    = g + 1024;

    const float* Wi = isL1 ? Wi1 : Wi0;
    const float* Wh = isL1 ? Wh1 : Wh0;
    const float* bi = isL1 ? bi1 : bi0;
    const float* bh = isL1 ? bh1 : bh0;

    // PyTorch gate rows: i=[0:6) f=[6:12) g=[12:18) o=[18:24).
    CellW W;
    const int   goff[4] = {0, 6, 12, 18};
    const float gscl[4] = {0.5f, 0.5f, 1.0f, 0.5f};
#pragma unroll
    for (int q = 0; q < 4; ++q) {
        const int   r = goff[q] + jj;
        const float s = gscl[q];
#pragma unroll
        for (int p = 0; p < 3; ++p) {
            W.wx[q][p] = pack2(s * Wi[r * 6 + 2 * p], s * Wi[r * 6 + 2 * p + 1]);
            W.wh[q][p] = pack2(s * Wh[r * 6 + 2 * p], s * Wh[r * 6 + 2 * p + 1]);
        }
        W.b[q] = pack2(s * (bi[r] + bh[r]), 0.f);
    }

    // State exchange: [parity][set][group][slot]; h0 at [0:6), h1 at [8:14).
    __shared__ __align__(16) float sbuf[2][2][8][16];
    sbuf[0][0][wg][lane & 15] = 0.f;
    sbuf[1][0][wg][lane & 15] = 0.f;
    sbuf[0][1][wg][lane & 15] = 0.f;
    sbuf[1][1][wg][lane & 15] = 0.f;

    const float* xbA = x + (size_t)bA * TT * 6;
    const float* xbB = x + (size_t)bB * TT * 6;

    float hA = 0.f, cA = 0.f, hB = 0.f, cB = 0.f;

    // x double buffers: 1 timestep (3 u64) per buffer per set.
    u64 uA[3], vA[3], uB[3], vB[3];
    loadstep(xbA, 0, vA); loadstep(xbB, 0, vB);   // t=0
    loadstep(xbA, 1, uA); loadstep(xbB, 1, uB);   // t=1

    // One timestep for both sets; parity P is compile-time.
#define STEP1(P, ZF, xA, xB)                                                    \
    do {                                                                        \
        __syncwarp();                                                           \
        one<ZF>(W, isL1, ro, slot, &sbuf[P][0][wg][0],                          \
                &sbuf[(P) ^ 1][0][wg][0], (xA), hA, cA);                        \
        one<ZF>(W, isL1, ro, slot, &sbuf[P][1][wg][0],                          \
                &sbuf[(P) ^ 1][1][wg][0], (xB), hB, cB);                        \
    } while (0)

    STEP1(0, true, vA, vB);                        // t=0 (reads zeroed parity 0)

#pragma unroll 1
    for (int t = 1; t < TT - 1; t += 2) {
        loadstep(xbA, t + 1, vA); loadstep(xbB, t + 1, vB);   // prefetch t+1
        STEP1(1, false, uA, uB);                              // t   (odd, parity 1)
        loadstep(xbA, t + 2, uA); loadstep(xbB, t + 2, uB);   // prefetch t+2 (<=2047)
        STEP1(0, false, vA, vB);                              // t+1 (even, parity 0)
    }
    // Loop covered t=1..2046. Remaining: t=2047 (odd, parity 1) in uA/uB.
    STEP1(1, false, uA, uB);                                  // t = 2047

    // Epilogue t=2048 (parity 0): layer 1 consumes h0(2047); L0 input zero.
    {
        u64 z[3] = {0ull, 0ull, 0ull};
        STEP1(0, false, z, z);
    }
#undef STEP1

    // Final h1 in parity-1 buffers, slots [8:14). Softmax per set.
    __syncwarp();
#pragma unroll
    for (int s = 0; s < 2; ++s) {
        const float* bb = &sbuf[1][s][wg][0];
        float hv[6];
#pragma unroll
        for (int k = 0; k < 6; ++k) hv[k] = bb[8 + k];
        float mx = hv[0];
#pragma unroll
        for (int k = 1; k < 6; ++k) mx = fmaxf(mx, hv[k]);
        float sum = 0.f, ev[6];
#pragma unroll
        for (int k = 0; k < 6; ++k) { ev[k] = __expf(hv[k] - mx); sum += ev[k]; }
        if (isL1 && j < 6) {
            const int bo = (s == 0) ? bA : bB;
            out[(size_t)bo * 6 + j] = __fdividef(ev[j], sum);
        }
    }
}

extern "C" void kernel_launch(void* const* d_in, const int* in_sizes, int n_in,
                              void* d_out, int out_size) {
    (void)in_sizes; (void)n_in; (void)out_size;
    const float* x   = (const float*)d_in[0];
    const float* Wi0 = (const float*)d_in[1];
    const float* Wh0 = (const float*)d_in[2];
    const float* bi0 = (const float*)d_in[3];
    const float* bh0 = (const float*)d_in[4];
    const float* Wi1 = (const float*)d_in[5];
    const float* Wh1 = (const float*)d_in[6];
    const float* bi1 = (const float*)d_in[7];
    const float* bh1 = (const float*)d_in[8];
    float* out = (float*)d_out;

    // 1024 batch-pairs * 16 lanes = 16384 threads = 128 blocks x 128 threads:
    // 1 block/SM on 128 SMs, 1 warp/SMSP, 2 independent chains per warp.
    stacked_lstm_kernel<<<128, 128>>>(x, Wi0, Wh0, bi0, bh0, Wi1, Wh1, bi1, bh1, out);
}

// round 15
// speedup vs baseline: 1.6090x; 1.6090x over previous
#include <cuda_runtime.h>

// StackedLSTM: B=2048, T=2048, D=H=6, 2 layers, softmax over final h of layer 1.
// 16 lanes/batch (lanes 0-7 layer 0, 8-15 layer 1), 2 warps/SMSP on 128 SMs.
// Layer 1 runs with lag 2 so its input-side work (and LDS) hoists PRE-barrier;
// only the recurrent path remains post-barrier. 4-slot smem ring, per-group
// syncwarp masks, gate-pair (i,f)/(g,o) f32x2 recurrent dots (no hadd on chain).

#define TT 2048

typedef unsigned long long u64;
typedef ulonglong2 u64x2;

static __device__ __forceinline__ u64 pack2(float lo, float hi) {
    u64 r; asm("mov.b64 %0, {%1, %2};" : "=l"(r) : "f"(lo), "f"(hi)); return r;
}
static __device__ __forceinline__ void unpack2(u64 v, float& lo, float& hi) {
    asm("mov.b64 {%0, %1}, %2;" : "=f"(lo), "=f"(hi) : "l"(v));
}
static __device__ __forceinline__ u64 ffma2(u64 a, u64 b, u64 c) {
    u64 d; asm("fma.rn.f32x2 %0, %1, %2, %3;" : "=l"(d) : "l"(a), "l"(b), "l"(c));
    return d;
}
static __device__ __forceinline__ u64 fadd2(u64 a, u64 b) {
    u64 d; asm("add.rn.f32x2 %0, %1, %2;" : "=l"(d) : "l"(a), "l"(b)); return d;
}
static __device__ __forceinline__ float tanh_f(float x) {
    float y; asm("tanh.approx.f32 %0, %1;" : "=f"(y) : "f"(x)); return y;
}

struct LaneW {
    u64 wxk[4][3];  // input-side: gate q, k-pair p ({w[q,2p], w[q,2p+1]}), prescaled
    u64 whIF[6];    // recurrent gate-pair (i,f): {w_i[k], w_f[k]}, prescaled
    u64 whGO[6];    // recurrent gate-pair (g,o): {w_g[k], 0.5*w_o[k]}
    u64 bs[4];      // {prescaled bias, 0} seeds for the input-side accumulators
};

// One iteration. P = iteration index mod 4 (compile-time).
// Ring usage at iteration n: write ring[n&3]; recurrent read ring[(n+3)&3]
// (written at n-1, fenced by this iteration's barrier); L1 input read
// ring[(n+2)&3] (written at n-2, fenced by the PREVIOUS barrier -> pre-barrier).
template <int P, bool ZF>
static __device__ __forceinline__ void iter(const LaneW& W, bool isL1, int ro, int slot,
                                            float* sb, unsigned gmask,
                                            const u64* xp, float& h, float& c) {
    // ---- pre-barrier: input-side gate sums (x(n) for L0, h0(n-2) for L1) ----
    const float* oh = sb + ((P + 2) & 3) * 256;       // 2-old h0, slots [0..5]
    u64x2 t01 = *(const u64x2*)oh;
    u64   t2  = ((const u64*)oh)[2];
    u64 inv0 = isL1 ? t01.x : xp[0];
    u64 inv1 = isL1 ? t01.y : xp[1];
    u64 inv2 = isL1 ? t2    : xp[2];
    float pis[4];
#pragma unroll
    for (int q = 0; q < 4; ++q) {
        u64 a = ffma2(W.wxk[q][0], inv0, W.bs[q]);
        a = ffma2(W.wxk[q][1], inv1, a);
        a = ffma2(W.wxk[q][2], inv2, a);
        float lo, hi; unpack2(a, lo, hi);
        pis[q] = lo + hi;
    }
    u64 pIF = pack2(pis[0], pis[1]);
    u64 pGO = pack2(pis[2], pis[3]);

    __syncwarp(gmask);

    // ---- post-barrier: recurrent side only ----
    const float* rc = sb + ((P + 3) & 3) * 256 + ro;  // own-layer h(n-1)
    float4 r0 = *(const float4*)rc;
    float2 r1 = *(const float2*)(rc + 4);
    u64 d0 = pack2(r0.x, r0.x), d1 = pack2(r0.y, r0.y), d2 = pack2(r0.z, r0.z);
    u64 d3 = pack2(r0.w, r0.w), d4 = pack2(r1.x, r1.x), d5 = pack2(r1.y, r1.y);

    u64 aIF = ffma2(W.whIF[0], d0, pIF);
    aIF = ffma2(W.whIF[1], d1, aIF);
    aIF = ffma2(W.whIF[2], d2, aIF);
    u64 bIF = ffma2(W.whIF[3], d3, 0ull);
    bIF = ffma2(W.whIF[4], d4, bIF);
    bIF = ffma2(W.whIF[5], d5, bIF);
    u64 gIF = fadd2(aIF, bIF);

    u64 aGO = ffma2(W.whGO[0], d0, pGO);
    aGO = ffma2(W.whGO[1], d1, aGO);
    aGO = ffma2(W.whGO[2], d2, aGO);
    u64 bGO = ffma2(W.whGO[3], d3, 0ull);
    bGO = ffma2(W.whGO[4], d4, bGO);
    bGO = ffma2(W.whGO[5], d5, bGO);
    u64 gGO = fadd2(aGO, bGO);

    float gi, gf, gg, go;
    unpack2(gIF, gi, gf);
    unpack2(gGO, gg, go);
    gi = fmaf(tanh_f(gi), 0.5f, 0.5f);
    gf = fmaf(tanh_f(gf), 0.5f, 0.5f);
    gg = tanh_f(gg);
    go = fmaf(tanh_f(go), 0.5f, 0.5f);
    c = fmaf(gf, c, gi * gg);
    h = go * tanh_f(c);
    if (ZF && isL1) { h = 0.f; c = 0.f; }   // L1's first two iterations are spurious
    sb[P * 256 + slot] = h;
}

static __device__ __forceinline__ void loadstep(const float* __restrict__ xb, int t, u64* u) {
    const u64* p = (const u64*)(xb + 6 * t);  // 24B stride, always 8B aligned
    u[0] = p[0]; u[1] = p[1]; u[2] = p[2];
}

__global__ void __launch_bounds__(256, 1)
stacked_lstm_kernel(const float* __restrict__ x,
                    const float* __restrict__ Wi0, const float* __restrict__ Wh0,
                    const float* __restrict__ bi0, const float* __restrict__ bh0,
                    const float* __restrict__ Wi1, const float* __restrict__ Wh1,
                    const float* __restrict__ bi1, const float* __restrict__ bh1,
                    float* __restrict__ out) {
    const int lane  = threadIdx.x & 31;
    const bool isL1 = (lane & 8) != 0;
    const int j     = lane & 7;
    const int jj    = (j < 6) ? j : 5;       // clamp for idle lanes 6,7
    const int ro    = isL1 ? 8 : 0;
    const int slot  = ro + j;
    const int wg    = threadIdx.x >> 4;      // group within block (0..15)
    const unsigned gmask = 0xFFFFu << (threadIdx.x & 16);
    const int b     = (blockIdx.x * blockDim.x + threadIdx.x) >> 4;  // batch

    const float* Wi = isL1 ? Wi1 : Wi0;
    const float* Wh = isL1 ? Wh1 : Wh0;
    const float* bi = isL1 ? bi1 : bi0;
    const float* bh = isL1 ? bh1 : bh0;

    // PyTorch gate rows: i=[0:6) f=[6:12) g=[12:18) o=[18:24).
    // Sigmoid gates (i,f,o) prescaled by 0.5: sig = .5 + .5*tanh(prescaled).
    LaneW W;
    const int   goff[4] = {0, 6, 12, 18};
    const float gscl[4] = {0.5f, 0.5f, 1.0f, 0.5f};
#pragma unroll
    for (int q = 0; q < 4; ++q) {
        const int   r = goff[q] + jj;
        const float s = gscl[q];
#pragma unroll
        for (int p = 0; p < 3; ++p)
            W.wxk[q][p] = pack2(s * Wi[r * 6 + 2 * p], s * Wi[r * 6 + 2 * p + 1]);
        W.bs[q] = pack2(s * (bi[r] + bh[r]), 0.f);
    }
#pragma unroll
    for (int k = 0; k < 6; ++k) {
        W.whIF[k] = pack2(0.5f * Wh[(0  + jj) * 6 + k], 0.5f * Wh[(6  + jj) * 6 + k]);
        W.whGO[k] = pack2(1.0f * Wh[(12 + jj) * 6 + k], 0.5f * Wh[(18 + jj) * 6 + k]);
    }

    // 4-ring state: ring r at sb + r*256; group region = 16 floats.
    __shared__ __align__(16) float sbuf[4 * 16 * 16];
    float* sb = sbuf + wg * 16;
#pragma unroll
    for (int r = 0; r < 4; ++r) sb[r * 256 + (lane & 15)] = 0.f;
    __syncwarp();

    const float* xb = x + (size_t)b * TT * 6;

    float h = 0.f, c = 0.f;

    u64 x0[3], x1[3];
    loadstep(xb, 0, x0);
    loadstep(xb, 1, x1);
    u64 XA[12], XB[12];
#pragma unroll
    for (int i = 0; i < 4; ++i) loadstep(xb, 2 + i, XA + 3 * i);
#pragma unroll
    for (int i = 0; i < 4; ++i) loadstep(xb, 6 + i, XB + 3 * i);

    // Peel n=0,1 (L1 spurious: zero-fixed).
    iter<0, true>(W, isL1, ro, slot, sb, gmask, x0, h, c);
    iter<1, true>(W, isL1, ro, slot, sb, gmask, x1, h, c);

    // Main loop: n = 2 .. 2049 (P pattern 2,3,0,1). 256 passes x 8 iterations.
#pragma unroll 1
    for (int m = 0; m < 512; m += 2) {
        const int n = 2 + 4 * m;
        // body A: n .. n+3
        iter<2, false>(W, isL1, ro, slot, sb, gmask, XA + 0, h, c);
        iter<3, false>(W, isL1, ro, slot, sb, gmask, XA + 3, h, c);
        iter<0, false>(W, isL1, ro, slot, sb, gmask, XA + 6, h, c);
        iter<1, false>(W, isL1, ro, slot, sb, gmask, XA + 9, h, c);
#pragma unroll
        for (int i = 0; i < 4; ++i) {
            int t = n + 8 + i; if (t > TT - 1) t = TT - 1;   // clamp: junk x only
            loadstep(xb, t, XA + 3 * i);                     // feeds junk L0 steps
        }
        // body B: n+4 .. n+7
        iter<2, false>(W, isL1, ro, slot, sb, gmask, XB + 0, h, c);
        iter<3, false>(W, isL1, ro, slot, sb, gmask, XB + 3, h, c);
        iter<0, false>(W, isL1, ro, slot, sb, gmask, XB + 6, h, c);
        iter<1, false>(W, isL1, ro, slot, sb, gmask, XB + 9, h, c);
#pragma unroll
        for (int i = 0; i < 4; ++i) {
            int t = n + 12 + i; if (t > TT - 1) t = TT - 1;
            loadstep(xb, t, XB + 3 * i);
        }
    }
    // Iterations executed: 2 + 2048 = 2050 (n=0..2049). With lag 2, L1's last
    // step (t=2047) ran at n=2049 (P=1) -> h1 final is in ring[1] slots [8:14).

    __syncwarp(gmask);
    {
        const float* fb = sb + 1 * 256;
        float hv[6];
#pragma unroll
        for (int k = 0; k < 6; ++k) hv[k] = fb[8 + k];
        float mx = hv[0];
#pragma unroll
        for (int k = 1; k < 6; ++k) mx = fmaxf(mx, hv[k]);
        float sum = 0.f, ev[6];
#pragma unroll
        for (int k = 0; k < 6; ++k) { ev[k] = __expf(hv[k] - mx); sum += ev[k]; }
        if (isL1 && j < 6)
            out[(size_t)b * 6 + j] = __fdividef(ev[j], sum);
    }
}

extern "C" void kernel_launch(void* const* d_in, const int* in_sizes, int n_in,
                              void* d_out, int out_size) {
    (void)in_sizes; (void)n_in; (void)out_size;
    const float* x   = (const float*)d_in[0];
    const float* Wi0 = (const float*)d_in[1];
    const float* Wh0 = (const float*)d_in[2];
    const float* bi0 = (const float*)d_in[3];
    const float* bh0 = (const float*)d_in[4];
    const float* Wi1 = (const float*)d_in[5];
    const float* Wh1 = (const float*)d_in[6];
    const float* bi1 = (const float*)d_in[7];
    const float* bh1 = (const float*)d_in[8];
    float* out = (float*)d_out;

    // 2048 batches * 16 lanes = 32768 threads = 128 blocks x 256 threads:
    // 1 block/SM on 128 SMs, 2 warps/SMSP (the proven best residency).
    stacked_lstm_kernel<<<128, 256>>>(x, Wi0, Wh0, bi0, bh0, Wi1, Wh1, bi1, bh1, out);
}